// round 12
// baseline (speedup 1.0000x reference)
#include <cuda_runtime.h>
#include <cuda_bf16.h>
#include <math.h>
#include <stdint.h>

#define NUM_Q   8
#define DIM     256
#define N_EMBED 1024
#define NROWS   65536
#define QOUT_ELEMS (NROWS * DIM)

#define MCTA   128
#define KTOT   768
#define KCH    64
#define NKC    12                  // k-chunks per n-tile
#define NNT    8                   // n-tiles of 128 codes
#define NCH    (NNT * NKC)         // 96 chunks
#define NBLK   (NROWS / MCTA)      // 512
#define THREADS 256
#define NWARP  8
#define TAU    0.05f
#define NC     4

// smem layout (bytes)
#define BUF_SZ   32768             // A(16KB)+B(16KB) per chunk buffer
#define OFF_EN   (4 * BUF_SZ)      // 131072: 1024 floats
#define OFF_RN   (OFF_EN + 4096)
#define OFF_IND  (OFF_RN + 512)
#define OFF_RED  (OFF_IND + 512)
#define OFF_CV   (OFF_RED + 128)
#define OFF_CI   (OFF_CV + 16384)
#define SMEM_TOTAL (OFF_CI + 16384)   // 169088

__device__ float g_res[NROWS * DIM];
__device__ float g_embT[NUM_Q * N_EMBED * DIM];
__device__ float g_norms[NUM_Q * N_EMBED];
__device__ float g_losspart[NUM_Q * NBLK];
__device__ int   g_counts[NUM_Q * N_EMBED];
__device__ __nv_bfloat16 g_Abf[(size_t)NROWS * KTOT];
__device__ __nv_bfloat16 g_Bbf[(size_t)NUM_Q * N_EMBED * KTOT];

__device__ __forceinline__ uint32_t smem_u32(const void* p) {
  uint32_t a;
  asm("{ .reg .u64 t; cvta.to.shared.u64 t, %1; cvt.u32.u64 %0, t; }"
      : "=r"(a) : "l"(p));
  return a;
}
__device__ __forceinline__ void cp16(uint32_t dst, const void* src) {
  asm volatile("cp.async.cg.shared.global [%0], [%1], 16;"
               :: "r"(dst), "l"(src) : "memory");
}
__device__ __forceinline__ void cp_commit() {
  asm volatile("cp.async.commit_group;" ::: "memory");
}
#define LDSM_X4(r0, r1, r2, r3, addr) \
  asm volatile("ldmatrix.sync.aligned.m8n8.x4.shared.b16 {%0,%1,%2,%3}, [%4];" \
      : "=r"(r0), "=r"(r1), "=r"(r2), "=r"(r3) : "r"(addr))
__device__ __forceinline__ void mma_bf16(float* d, const uint32_t* a,
                                         uint32_t b0, uint32_t b1) {
  asm volatile(
      "mma.sync.aligned.m16n8k16.row.col.f32.bf16.bf16.f32 "
      "{%0,%1,%2,%3}, {%4,%5,%6,%7}, {%8,%9}, {%0,%1,%2,%3};"
      : "+f"(d[0]), "+f"(d[1]), "+f"(d[2]), "+f"(d[3])
      : "r"(a[0]), "r"(a[1]), "r"(a[2]), "r"(a[3]), "r"(b0), "r"(b1));
}
__device__ __forceinline__ void ins4(float v, int c, float* cv, int* ci) {
  if (v < cv[NC - 1]) {
    float pv = v; int pc = c;
    #pragma unroll
    for (int q = 0; q < NC; ++q) {
      if (pv < cv[q]) {
        float tv = cv[q]; int tc = ci[q];
        cv[q] = pv; ci[q] = pc; pv = tv; pc = tc;
      }
    }
  }
}

// ---------------- prep: embT transpose + counts zero + B bf16 split ----------------
__global__ void prep_kernel(const float* __restrict__ embeds) {
  int idx = blockIdx.x * 256 + threadIdx.x;   // over [l][d][k]
  int l = idx >> 18;
  int rem = idx & 262143;
  int d = rem >> 10;
  int k = rem & 1023;
  float v = embeds[idx];
  g_embT[((size_t)l * N_EMBED + k) * DIM + d] = v;
  __nv_bfloat16 hi = __float2bfloat16(v);
  __nv_bfloat16 lo = __float2bfloat16(__fsub_rn(v, __bfloat162float(hi)));
  __nv_bfloat16* b = g_Bbf + ((size_t)l * N_EMBED + k) * KTOT;
  b[d] = hi; b[256 + d] = lo; b[512 + d] = hi;   // B = [e_hi | e_lo | e_hi]
  if (idx < NUM_Q * N_EMBED) g_counts[idx] = 0;
}

// ---------------- code norms: sequential d, separate mul+add ----------------
__global__ void norms_kernel(const float* __restrict__ embeds) {
  int k = blockIdx.x * 256 + threadIdx.x;
  int l = k >> 10;
  int kk = k & 1023;
  float s = 0.f;
  for (int d = 0; d < DIM; ++d) {
    float v = embeds[((size_t)l * DIM + d) * N_EMBED + kk];
    s = __fadd_rn(s, __fmul_rn(v, v));
  }
  g_norms[k] = s;
}

// ---------------- layer-0 A bf16 split: A = [r_hi | r_hi | r_lo] ----------------
__global__ void convertA_kernel(const float* __restrict__ x) {
  size_t idx = (size_t)blockIdx.x * 256 + threadIdx.x;
  float v = x[idx];
  int row = (int)(idx >> 8);
  int d = (int)(idx & 255);
  __nv_bfloat16 hi = __float2bfloat16(v);
  __nv_bfloat16 lo = __float2bfloat16(__fsub_rn(v, __bfloat162float(hi)));
  __nv_bfloat16* a = g_Abf + (size_t)row * KTOT;
  a[d] = hi; a[256 + d] = hi; a[512 + d] = lo;
}

// ---------------- main fused VQ layer: ldmatrix + mma.sync bf16 + exact rescore ----------------
__global__ void __launch_bounds__(THREADS)
vq_mma_kernel(const float* __restrict__ x,
              float* __restrict__ qout,
              int layer) {
  extern __shared__ char sm[];
  const uint32_t sbase = smem_u32(sm);
  float* sEN  = (float*)(sm + OFF_EN);
  float* sRN  = (float*)(sm + OFF_RN);
  int*   sInd = (int*)(sm + OFF_IND);
  float* sRed = (float*)(sm + OFF_RED);
  float* sCV  = (float*)(sm + OFF_CV);
  int*   sCI  = (int*)(sm + OFF_CI);

  const int tid = threadIdx.x, wid = tid >> 5, lane = tid & 31;
  const int mw = wid & 3;          // m-warp: rows mw*32..+31
  const int nw = wid >> 2;         // n-warp: codes nw*64..+63 within tile
  const int lr = lane >> 2;        // 0..7
  const int lc = lane & 3;         // 0..3

  const float* resin = (layer == 0) ? x : g_res;
  const float* rbase = resin + (size_t)blockIdx.x * MCTA * DIM;
  const __nv_bfloat16* Ag = g_Abf + (size_t)blockIdx.x * MCTA * KTOT;
  const __nv_bfloat16* Bg = g_Bbf + (size_t)layer * N_EMBED * KTOT;

  // ldmatrix per-lane base offsets (bytes), swizzle baked in
  const int rowA0 = mw * 32 + (lane & 15);
  const int rowA1 = rowA0 + 16;
  const int halfA = lane >> 4;
  const uint32_t preA0 = (uint32_t)(rowA0 * 32 + ((halfA ^ ((rowA0 >> 2) & 1)) * 16));
  const uint32_t preA1 = (uint32_t)(rowA1 * 32 + ((halfA ^ ((rowA1 >> 2) & 1)) * 16));
  const int rowB  = nw * 64 + (lane & 7) + ((lane >> 4) & 1) * 8;
  const int halfB = (lane >> 3) & 1;
  const uint32_t preB = (uint32_t)(rowB * 32 + ((halfB ^ ((rowB >> 2) & 1)) * 16));

  // code norms into smem
  for (int i = tid; i < N_EMBED; i += THREADS)
    sEN[i] = g_norms[layer * N_EMBED + i];

  // ---- ||r||^2 per row (XLA row-reduce pattern; 16 rows per warp) ----
  #pragma unroll 1
  for (int rr = 0; rr < 16; ++rr) {
    int row = wid * 16 + rr;
    const float* rp = rbase + row * DIM;
    float p0 = 0.f, p1 = 0.f;
    #pragma unroll
    for (int i = 0; i < 4; ++i) {
      float2 v = __ldg((const float2*)&rp[i * 64 + 2 * lane]);
      p0 = __fadd_rn(p0, __fmul_rn(v.x, v.x));
      p1 = __fadd_rn(p1, __fmul_rn(v.y, v.y));
    }
    float a = __fadd_rn(p0, p1);
    #pragma unroll
    for (int off = 16; off > 0; off >>= 1)
      a = __fadd_rn(a, __shfl_down_sync(0xffffffff, a, off));
    if (lane == 0) sRN[row] = a;
  }

  // chunk fill via cp.async (layout: [ks][row][half], half-bit XOR swizzle)
  auto fill = [&](int ch) {
    const int nt = ch / NKC, kc = ch - nt * NKC;
    const uint32_t base = sbase + (uint32_t)(ch & 3) * BUF_SZ;
    #pragma unroll
    for (int t = 0; t < 4; ++t) {
      int idx = tid + t * THREADS;      // 0..1023
      int row = idx >> 3, seg = idx & 7;
      int ks = seg >> 1, half = seg & 1;
      uint32_t off = (uint32_t)(ks * 4096 + row * 32
                                + ((half ^ ((row >> 2) & 1)) * 16));
      cp16(base + off, Ag + (size_t)row * KTOT + kc * KCH + seg * 8);
      cp16(base + 16384 + off,
           Bg + (size_t)(nt * 128 + row) * KTOT + kc * KCH + seg * 8);
    }
    cp_commit();
  };

  fill(0); fill(1); fill(2);

  float acc[2][8][4];
  float cv[4][NC]; int ci[4][NC];
  #pragma unroll
  for (int li = 0; li < 4; ++li)
    #pragma unroll
    for (int q = 0; q < NC; ++q) { cv[li][q] = 3.4028235e38f; ci[li][q] = 0; }

  for (int c = 0; c < NCH; ++c) {
    const int nt = c / NKC, kc = c - nt * NKC;

    if (c <= NCH - 3)      asm volatile("cp.async.wait_group 2;" ::: "memory");
    else if (c == NCH - 2) asm volatile("cp.async.wait_group 1;" ::: "memory");
    else                   asm volatile("cp.async.wait_group 0;" ::: "memory");
    __syncthreads();

    if (kc == 0) {
      #pragma unroll
      for (int i = 0; i < 2; ++i)
        #pragma unroll
        for (int j = 0; j < 8; ++j)
          #pragma unroll
          for (int q = 0; q < 4; ++q) acc[i][j][q] = 0.f;
    }

    const uint32_t base = sbase + (uint32_t)(c & 3) * BUF_SZ;
    #pragma unroll
    for (int ks = 0; ks < 4; ++ks) {
      uint32_t a0[4], a1[4];
      LDSM_X4(a0[0], a0[1], a0[2], a0[3], base + preA0 + ks * 4096);
      LDSM_X4(a1[0], a1[1], a1[2], a1[3], base + preA1 + ks * 4096);
      #pragma unroll
      for (int p = 0; p < 4; ++p) {
        uint32_t b0, b1, b2, b3;
        LDSM_X4(b0, b1, b2, b3, base + 16384 + preB + ks * 4096 + p * 512);
        mma_bf16(acc[0][p * 2],     a0, b0, b1);
        mma_bf16(acc[0][p * 2 + 1], a0, b2, b3);
        mma_bf16(acc[1][p * 2],     a1, b0, b1);
        mma_bf16(acc[1][p * 2 + 1], a1, b2, b3);
      }
    }

    if (kc == NKC - 1) {
      const int C00 = nt * 128 + nw * 64 + lc * 2;
      #pragma unroll
      for (int i = 0; i < 2; ++i) {
        #pragma unroll
        for (int j = 0; j < 8; ++j) {
          int code0 = C00 + j * 8;
          float e0 = sEN[code0], e1 = sEN[code0 + 1];
          ins4(__fmaf_rn(-2.f, acc[i][j][0], e0), code0,     cv[i * 2],     ci[i * 2]);
          ins4(__fmaf_rn(-2.f, acc[i][j][1], e1), code0 + 1, cv[i * 2],     ci[i * 2]);
          ins4(__fmaf_rn(-2.f, acc[i][j][2], e0), code0,     cv[i * 2 + 1], ci[i * 2 + 1]);
          ins4(__fmaf_rn(-2.f, acc[i][j][3], e1), code0 + 1, cv[i * 2 + 1], ci[i * 2 + 1]);
        }
      }
    }

    if (c + 3 < NCH) fill(c + 3);
  }

  // dump candidates: row r has 32 slots (2 nw x 4 lc x NC)
  {
    const int slot = nw * 16 + lc * 4;
    #pragma unroll
    for (int i = 0; i < 2; ++i)
      #pragma unroll
      for (int a = 0; a < 2; ++a) {
        int r = mw * 32 + i * 16 + a * 8 + lr;
        int li = i * 2 + a;
        #pragma unroll
        for (int q = 0; q < NC; ++q) {
          sCV[r * 32 + slot + q] = cv[li][q];
          sCI[r * 32 + slot + q] = ci[li][q];
        }
      }
  }
  __syncthreads();

  // ---- exact rescore (bit-identical reference chain) ----
  if (tid < MCTA) {
    const int r = tid;
    float vmin = 3.4028235e38f;
    #pragma unroll 4
    for (int s = 0; s < 32; ++s) vmin = fminf(vmin, sCV[r * 32 + s]);
    const float thr = vmin + TAU;
    const float rn = sRN[r];
    const float* rp = rbase + r * DIM;
    float bestd = 3.4028235e38f;
    int   bestc = 0x7fffffff;
    #pragma unroll 1
    for (int s = 0; s < 32; ++s) {
      if (sCV[r * 32 + s] <= thr) {
        int code = sCI[r * 32 + s];
        const float* ep = g_embT + ((size_t)layer * N_EMBED + code) * DIM;
        float ab = 0.f;
        #pragma unroll 8
        for (int d4 = 0; d4 < 64; ++d4) {
          float4 rv = __ldg((const float4*)rp + d4);
          float4 ev = __ldg((const float4*)ep + d4);
          ab = __fmaf_rn(rv.x, ev.x, ab);
          ab = __fmaf_rn(rv.y, ev.y, ab);
          ab = __fmaf_rn(rv.z, ev.z, ab);
          ab = __fmaf_rn(rv.w, ev.w, ab);
        }
        float en = sEN[code];
        float dist = __fadd_rn(__fadd_rn(rn, __fmul_rn(-2.0f, ab)), en);
        if (dist < bestd || (dist == bestd && code < bestc)) {
          bestd = dist; bestc = code;
        }
      }
    }
    sInd[r] = bestc;
  }
  __syncthreads();

  // ---- straight-through epilogue (exact chain) + fused next-layer A split ----
  float lsum = 0.f;
  const size_t rowbase = (size_t)blockIdx.x * MCTA;
  #pragma unroll 1
  for (int rr = 0; rr < 16; ++rr) {
    int r = wid * 16 + rr;
    int cc = sInd[r];
    const float* q   = g_embT + ((size_t)layer * N_EMBED + cc) * DIM;
    float* outp      = qout  + (rowbase + r) * DIM;
    float* resp      = g_res + (rowbase + r) * DIM;
    const float* rsm = rbase + r * DIM;
    __nv_bfloat16* arow = g_Abf + (rowbase + r) * KTOT;
    #pragma unroll
    for (int h = 0; h < 2; ++h) {
      int d = lane * 4 + h * 128;
      float4 qv = __ldg((const float4*)(q + d));
      float4 rv = __ldg((const float4*)(rsm + d));
      float4 dq, qst, nr;
      dq.x = __fadd_rn(qv.x, -rv.x); dq.y = __fadd_rn(qv.y, -rv.y);
      dq.z = __fadd_rn(qv.z, -rv.z); dq.w = __fadd_rn(qv.w, -rv.w);
      qst.x = __fadd_rn(rv.x, dq.x); qst.y = __fadd_rn(rv.y, dq.y);
      qst.z = __fadd_rn(rv.z, dq.z); qst.w = __fadd_rn(rv.w, dq.w);
      nr.x = __fadd_rn(rv.x, -qst.x); nr.y = __fadd_rn(rv.y, -qst.y);
      nr.z = __fadd_rn(rv.z, -qst.z); nr.w = __fadd_rn(rv.w, -qst.w);
      *(float4*)(resp + d) = nr;
      float4 ov;
      if (layer == 0) {
        ov = qst;
      } else {
        ov = *(const float4*)(outp + d);
        ov.x = __fadd_rn(ov.x, qst.x); ov.y = __fadd_rn(ov.y, qst.y);
        ov.z = __fadd_rn(ov.z, qst.z); ov.w = __fadd_rn(ov.w, qst.w);
      }
      *(float4*)(outp + d) = ov;
      lsum += __fmul_rn(dq.x, dq.x) + __fmul_rn(dq.y, dq.y)
            + __fmul_rn(dq.z, dq.z) + __fmul_rn(dq.w, dq.w);
      if (layer < NUM_Q - 1) {
        __nv_bfloat16 hx = __float2bfloat16(nr.x);
        __nv_bfloat16 hy = __float2bfloat16(nr.y);
        __nv_bfloat16 hz = __float2bfloat16(nr.z);
        __nv_bfloat16 hw = __float2bfloat16(nr.w);
        __nv_bfloat16 lx = __float2bfloat16(__fsub_rn(nr.x, __bfloat162float(hx)));
        __nv_bfloat16 ly = __float2bfloat16(__fsub_rn(nr.y, __bfloat162float(hy)));
        __nv_bfloat16 lz = __float2bfloat16(__fsub_rn(nr.z, __bfloat162float(hz)));
        __nv_bfloat16 lw = __float2bfloat16(__fsub_rn(nr.w, __bfloat162float(hw)));
        __nv_bfloat162 h01, h23, l01, l23;
        h01.x = hx; h01.y = hy; h23.x = hz; h23.y = hw;
        l01.x = lx; l01.y = ly; l23.x = lz; l23.y = lw;
        uint2 hv, lv;
        hv.x = *(uint32_t*)&h01; hv.y = *(uint32_t*)&h23;
        lv.x = *(uint32_t*)&l01; lv.y = *(uint32_t*)&l23;
        *(uint2*)(arow + d)       = hv;
        *(uint2*)(arow + 256 + d) = hv;
        *(uint2*)(arow + 512 + d) = lv;
      }
    }
    if (lane == 0) atomicAdd(&g_counts[layer * N_EMBED + cc], 1);
  }
  #pragma unroll
  for (int off = 16; off > 0; off >>= 1)
    lsum += __shfl_xor_sync(0xffffffff, lsum, off);
  if (lane == 0) sRed[wid] = lsum;
  __syncthreads();
  if (tid == 0) {
    float s = 0.f;
    #pragma unroll
    for (int w = 0; w < NWARP; ++w) s += sRed[w];
    g_losspart[layer * NBLK + blockIdx.x] = s;
  }
}

// ---------------- finalize: loss mean + perplexity ----------------
__global__ void finalize_kernel(float* __restrict__ out) {
  const int l = blockIdx.x;
  const int tid = threadIdx.x;
  __shared__ double sd[256];
  __shared__ float  sf[256];
  double ls = 0.0;
  float  es = 0.f;
  for (int i = tid; i < NBLK; i += 256)
    ls += (double)g_losspart[l * NBLK + i];
  for (int i = tid; i < N_EMBED; i += 256) {
    float p = (float)g_counts[l * N_EMBED + i] * (1.0f / (float)NROWS);
    es += p * logf(__fadd_rn(p, 1e-10f));
  }
  sd[tid] = ls; sf[tid] = es;
  __syncthreads();
  for (int s = 128; s > 0; s >>= 1) {
    if (tid < s) { sd[tid] += sd[tid + s]; sf[tid] += sf[tid + s]; }
    __syncthreads();
  }
  if (tid == 0) {
    out[QOUT_ELEMS + l]         = (float)(sd[0] / (double)QOUT_ELEMS);
    out[QOUT_ELEMS + NUM_Q + l] = expf(-sf[0]);
  }
}

extern "C" void kernel_launch(void* const* d_in, const int* in_sizes, int n_in,
                              void* d_out, int out_size) {
  const float* x      = (const float*)d_in[0];
  const float* embeds = (const float*)d_in[1];
  float* out          = (float*)d_out;

  cudaFuncSetAttribute(vq_mma_kernel,
                       cudaFuncAttributeMaxDynamicSharedMemorySize, SMEM_TOTAL);

  prep_kernel<<<(NUM_Q * N_EMBED * DIM) / 256, 256>>>(embeds);
  norms_kernel<<<(NUM_Q * N_EMBED) / 256, 256>>>(embeds);
  convertA_kernel<<<(NROWS * DIM) / 256, 256>>>(x);

  for (int l = 0; l < NUM_Q; ++l) {
    vq_mma_kernel<<<NBLK, THREADS, SMEM_TOTAL>>>(x, out, l);
  }
  finalize_kernel<<<NUM_Q, 256>>>(out);
}

// round 13
// speedup vs baseline: 1.1275x; 1.1275x over previous
#include <cuda_runtime.h>
#include <cuda_bf16.h>
#include <math.h>
#include <stdint.h>

#define NUM_Q   8
#define DIM     256
#define N_EMBED 1024
#define NROWS   65536
#define QOUT_ELEMS (NROWS * DIM)

#define MCTA   128
#define KTOT   768
#define KCH    64
#define NKC    12                  // k-chunks per n-tile
#define NNT    8                   // n-tiles of 128 codes
#define NCH    (NNT * NKC)         // 96 chunks
#define NBLK   (NROWS / MCTA)      // 512
#define THREADS 256
#define NWARP  8
#define TAU    0.05f
#define NC     4

// smem layout (bytes) — 2 pipeline buffers for 2 CTAs/SM
#define BUF_SZ   32768             // A(16KB)+B(16KB) per chunk buffer
#define OFF_EN   (2 * BUF_SZ)      // 65536: 1024 floats
#define OFF_RN   (OFF_EN + 4096)   // 69632
#define OFF_IND  (OFF_RN + 512)    // 70144
#define OFF_RED  (OFF_IND + 512)   // 70656
#define OFF_CV   (OFF_RED + 128)   // 70784
#define OFF_CI   (OFF_CV + 16384)  // 87168
#define SMEM_TOTAL (OFF_CI + 16384)   // 103552

__device__ float g_res[NROWS * DIM];
__device__ float g_embT[NUM_Q * N_EMBED * DIM];
__device__ float g_norms[NUM_Q * N_EMBED];
__device__ float g_losspart[NUM_Q * NBLK];
__device__ int   g_counts[NUM_Q * N_EMBED];
__device__ __nv_bfloat16 g_Abf[(size_t)NROWS * KTOT];
__device__ __nv_bfloat16 g_Bbf[(size_t)NUM_Q * N_EMBED * KTOT];

__device__ __forceinline__ uint32_t smem_u32(const void* p) {
  uint32_t a;
  asm("{ .reg .u64 t; cvta.to.shared.u64 t, %1; cvt.u32.u64 %0, t; }"
      : "=r"(a) : "l"(p));
  return a;
}
__device__ __forceinline__ void cp16(uint32_t dst, const void* src) {
  asm volatile("cp.async.cg.shared.global [%0], [%1], 16;"
               :: "r"(dst), "l"(src) : "memory");
}
__device__ __forceinline__ void cp_commit() {
  asm volatile("cp.async.commit_group;" ::: "memory");
}
#define LDSM_X4(r0, r1, r2, r3, addr) \
  asm volatile("ldmatrix.sync.aligned.m8n8.x4.shared.b16 {%0,%1,%2,%3}, [%4];" \
      : "=r"(r0), "=r"(r1), "=r"(r2), "=r"(r3) : "r"(addr))
__device__ __forceinline__ void mma_bf16(float* d, const uint32_t* a,
                                         uint32_t b0, uint32_t b1) {
  asm volatile(
      "mma.sync.aligned.m16n8k16.row.col.f32.bf16.bf16.f32 "
      "{%0,%1,%2,%3}, {%4,%5,%6,%7}, {%8,%9}, {%0,%1,%2,%3};"
      : "+f"(d[0]), "+f"(d[1]), "+f"(d[2]), "+f"(d[3])
      : "r"(a[0]), "r"(a[1]), "r"(a[2]), "r"(a[3]), "r"(b0), "r"(b1));
}
__device__ __forceinline__ void ins4(float v, int c, float* cv, int* ci) {
  if (v < cv[NC - 1]) {
    float pv = v; int pc = c;
    #pragma unroll
    for (int q = 0; q < NC; ++q) {
      if (pv < cv[q]) {
        float tv = cv[q]; int tc = ci[q];
        cv[q] = pv; ci[q] = pc; pv = tv; pc = tc;
      }
    }
  }
}

// ---------------- prep: embT transpose + counts zero + B bf16 split ----------------
__global__ void prep_kernel(const float* __restrict__ embeds) {
  int idx = blockIdx.x * 256 + threadIdx.x;   // over [l][d][k]
  int l = idx >> 18;
  int rem = idx & 262143;
  int d = rem >> 10;
  int k = rem & 1023;
  float v = embeds[idx];
  g_embT[((size_t)l * N_EMBED + k) * DIM + d] = v;
  __nv_bfloat16 hi = __float2bfloat16(v);
  __nv_bfloat16 lo = __float2bfloat16(__fsub_rn(v, __bfloat162float(hi)));
  __nv_bfloat16* b = g_Bbf + ((size_t)l * N_EMBED + k) * KTOT;
  b[d] = hi; b[256 + d] = lo; b[512 + d] = hi;   // B = [e_hi | e_lo | e_hi]
  if (idx < NUM_Q * N_EMBED) g_counts[idx] = 0;
}

// ---------------- code norms: sequential d, separate mul+add ----------------
__global__ void norms_kernel(const float* __restrict__ embeds) {
  int k = blockIdx.x * 256 + threadIdx.x;
  int l = k >> 10;
  int kk = k & 1023;
  float s = 0.f;
  for (int d = 0; d < DIM; ++d) {
    float v = embeds[((size_t)l * DIM + d) * N_EMBED + kk];
    s = __fadd_rn(s, __fmul_rn(v, v));
  }
  g_norms[k] = s;
}

// ---------------- layer-0 A bf16 split: A = [r_hi | r_hi | r_lo] ----------------
__global__ void convertA_kernel(const float* __restrict__ x) {
  size_t idx = (size_t)blockIdx.x * 256 + threadIdx.x;
  float v = x[idx];
  int row = (int)(idx >> 8);
  int d = (int)(idx & 255);
  __nv_bfloat16 hi = __float2bfloat16(v);
  __nv_bfloat16 lo = __float2bfloat16(__fsub_rn(v, __bfloat162float(hi)));
  __nv_bfloat16* a = g_Abf + (size_t)row * KTOT;
  a[d] = hi; a[256 + d] = hi; a[512 + d] = lo;
}

// ---------------- main fused VQ layer: ldmatrix + mma.sync bf16 + exact rescore ----------------
__global__ void __launch_bounds__(THREADS, 2)
vq_mma_kernel(const float* __restrict__ x,
              float* __restrict__ qout,
              int layer) {
  extern __shared__ char sm[];
  const uint32_t sbase = smem_u32(sm);
  float* sEN  = (float*)(sm + OFF_EN);
  float* sRN  = (float*)(sm + OFF_RN);
  int*   sInd = (int*)(sm + OFF_IND);
  float* sRed = (float*)(sm + OFF_RED);
  float* sCV  = (float*)(sm + OFF_CV);
  int*   sCI  = (int*)(sm + OFF_CI);

  const int tid = threadIdx.x, wid = tid >> 5, lane = tid & 31;
  const int mw = wid & 3;          // m-warp: rows mw*32..+31
  const int nw = wid >> 2;         // n-warp: codes nw*64..+63 within tile
  const int lr = lane >> 2;        // 0..7
  const int lc = lane & 3;         // 0..3

  const float* resin = (layer == 0) ? x : g_res;
  const float* rbase = resin + (size_t)blockIdx.x * MCTA * DIM;
  const __nv_bfloat16* Ag = g_Abf + (size_t)blockIdx.x * MCTA * KTOT;
  const __nv_bfloat16* Bg = g_Bbf + (size_t)layer * N_EMBED * KTOT;

  // ldmatrix per-lane base offsets (bytes), swizzle baked in
  const int rowA0 = mw * 32 + (lane & 15);
  const int rowA1 = rowA0 + 16;
  const int halfA = lane >> 4;
  const uint32_t preA0 = (uint32_t)(rowA0 * 32 + ((halfA ^ ((rowA0 >> 2) & 1)) * 16));
  const uint32_t preA1 = (uint32_t)(rowA1 * 32 + ((halfA ^ ((rowA1 >> 2) & 1)) * 16));
  const int rowB  = nw * 64 + (lane & 7) + ((lane >> 4) & 1) * 8;
  const int halfB = (lane >> 3) & 1;
  const uint32_t preB = (uint32_t)(rowB * 32 + ((halfB ^ ((rowB >> 2) & 1)) * 16));

  // code norms into smem
  for (int i = tid; i < N_EMBED; i += THREADS)
    sEN[i] = g_norms[layer * N_EMBED + i];

  // ---- ||r||^2 per row (XLA row-reduce pattern; 16 rows per warp) ----
  #pragma unroll 1
  for (int rr = 0; rr < 16; ++rr) {
    int row = wid * 16 + rr;
    const float* rp = rbase + row * DIM;
    float p0 = 0.f, p1 = 0.f;
    #pragma unroll
    for (int i = 0; i < 4; ++i) {
      float2 v = __ldg((const float2*)&rp[i * 64 + 2 * lane]);
      p0 = __fadd_rn(p0, __fmul_rn(v.x, v.x));
      p1 = __fadd_rn(p1, __fmul_rn(v.y, v.y));
    }
    float a = __fadd_rn(p0, p1);
    #pragma unroll
    for (int off = 16; off > 0; off >>= 1)
      a = __fadd_rn(a, __shfl_down_sync(0xffffffff, a, off));
    if (lane == 0) sRN[row] = a;
  }

  // chunk fill via cp.async (layout: [ks][row][half], half-bit XOR swizzle)
  auto fill = [&](int ch) {
    const int nt = ch / NKC, kc = ch - nt * NKC;
    const uint32_t base = sbase + (uint32_t)(ch & 1) * BUF_SZ;
    #pragma unroll
    for (int t = 0; t < 4; ++t) {
      int idx = tid + t * THREADS;      // 0..1023
      int row = idx >> 3, seg = idx & 7;
      int ks = seg >> 1, half = seg & 1;
      uint32_t off = (uint32_t)(ks * 4096 + row * 32
                                + ((half ^ ((row >> 2) & 1)) * 16));
      cp16(base + off, Ag + (size_t)row * KTOT + kc * KCH + seg * 8);
      cp16(base + 16384 + off,
           Bg + (size_t)(nt * 128 + row) * KTOT + kc * KCH + seg * 8);
    }
    cp_commit();
  };

  fill(0); fill(1);

  float acc[2][8][4];
  float cv[4][NC]; int ci[4][NC];
  #pragma unroll
  for (int li = 0; li < 4; ++li)
    #pragma unroll
    for (int q = 0; q < NC; ++q) { cv[li][q] = 3.4028235e38f; ci[li][q] = 0; }

  for (int c = 0; c < NCH; ++c) {
    const int nt = c / NKC, kc = c - nt * NKC;

    if (c + 1 < NCH) asm volatile("cp.async.wait_group 1;" ::: "memory");
    else             asm volatile("cp.async.wait_group 0;" ::: "memory");
    __syncthreads();

    if (kc == 0) {
      #pragma unroll
      for (int i = 0; i < 2; ++i)
        #pragma unroll
        for (int j = 0; j < 8; ++j)
          #pragma unroll
          for (int q = 0; q < 4; ++q) acc[i][j][q] = 0.f;
    }

    const uint32_t base = sbase + (uint32_t)(c & 1) * BUF_SZ;
    #pragma unroll
    for (int ks = 0; ks < 4; ++ks) {
      uint32_t a0[4], a1[4];
      LDSM_X4(a0[0], a0[1], a0[2], a0[3], base + preA0 + ks * 4096);
      LDSM_X4(a1[0], a1[1], a1[2], a1[3], base + preA1 + ks * 4096);
      #pragma unroll
      for (int p = 0; p < 4; ++p) {
        uint32_t b0, b1, b2, b3;
        LDSM_X4(b0, b1, b2, b3, base + 16384 + preB + ks * 4096 + p * 512);
        mma_bf16(acc[0][p * 2],     a0, b0, b1);
        mma_bf16(acc[0][p * 2 + 1], a0, b2, b3);
        mma_bf16(acc[1][p * 2],     a1, b0, b1);
        mma_bf16(acc[1][p * 2 + 1], a1, b2, b3);
      }
    }

    if (kc == NKC - 1) {
      const int C00 = nt * 128 + nw * 64 + lc * 2;
      #pragma unroll
      for (int i = 0; i < 2; ++i) {
        #pragma unroll
        for (int j = 0; j < 8; ++j) {
          int code0 = C00 + j * 8;
          float e0 = sEN[code0], e1 = sEN[code0 + 1];
          ins4(__fmaf_rn(-2.f, acc[i][j][0], e0), code0,     cv[i * 2],     ci[i * 2]);
          ins4(__fmaf_rn(-2.f, acc[i][j][1], e1), code0 + 1, cv[i * 2],     ci[i * 2]);
          ins4(__fmaf_rn(-2.f, acc[i][j][2], e0), code0,     cv[i * 2 + 1], ci[i * 2 + 1]);
          ins4(__fmaf_rn(-2.f, acc[i][j][3], e1), code0 + 1, cv[i * 2 + 1], ci[i * 2 + 1]);
        }
      }
    }

    __syncthreads();                  // all warps done reading buffer (c&1)
    if (c + 2 < NCH) fill(c + 2);     // refill it for chunk c+2
  }

  // dump candidates: row r has 32 slots (2 nw x 4 lc x NC)
  {
    const int slot = nw * 16 + lc * 4;
    #pragma unroll
    for (int i = 0; i < 2; ++i)
      #pragma unroll
      for (int a = 0; a < 2; ++a) {
        int r = mw * 32 + i * 16 + a * 8 + lr;
        int li = i * 2 + a;
        #pragma unroll
        for (int q = 0; q < NC; ++q) {
          sCV[r * 32 + slot + q] = cv[li][q];
          sCI[r * 32 + slot + q] = ci[li][q];
        }
      }
  }
  __syncthreads();

  // ---- exact rescore (bit-identical reference chain) ----
  if (tid < MCTA) {
    const int r = tid;
    float vmin = 3.4028235e38f;
    #pragma unroll 4
    for (int s = 0; s < 32; ++s) vmin = fminf(vmin, sCV[r * 32 + s]);
    const float thr = vmin + TAU;
    const float rn = sRN[r];
    const float* rp = rbase + r * DIM;
    float bestd = 3.4028235e38f;
    int   bestc = 0x7fffffff;
    #pragma unroll 1
    for (int s = 0; s < 32; ++s) {
      if (sCV[r * 32 + s] <= thr) {
        int code = sCI[r * 32 + s];
        const float* ep = g_embT + ((size_t)layer * N_EMBED + code) * DIM;
        float ab = 0.f;
        #pragma unroll 8
        for (int d4 = 0; d4 < 64; ++d4) {
          float4 rv = __ldg((const float4*)rp + d4);
          float4 ev = __ldg((const float4*)ep + d4);
          ab = __fmaf_rn(rv.x, ev.x, ab);
          ab = __fmaf_rn(rv.y, ev.y, ab);
          ab = __fmaf_rn(rv.z, ev.z, ab);
          ab = __fmaf_rn(rv.w, ev.w, ab);
        }
        float en = sEN[code];
        float dist = __fadd_rn(__fadd_rn(rn, __fmul_rn(-2.0f, ab)), en);
        if (dist < bestd || (dist == bestd && code < bestc)) {
          bestd = dist; bestc = code;
        }
      }
    }
    sInd[r] = bestc;
  }
  __syncthreads();

  // ---- straight-through epilogue (exact chain) + fused next-layer A split ----
  float lsum = 0.f;
  const size_t rowbase = (size_t)blockIdx.x * MCTA;
  #pragma unroll 1
  for (int rr = 0; rr < 16; ++rr) {
    int r = wid * 16 + rr;
    int cc = sInd[r];
    const float* q   = g_embT + ((size_t)layer * N_EMBED + cc) * DIM;
    float* outp      = qout  + (rowbase + r) * DIM;
    float* resp      = g_res + (rowbase + r) * DIM;
    const float* rsm = rbase + r * DIM;
    __nv_bfloat16* arow = g_Abf + (rowbase + r) * KTOT;
    #pragma unroll
    for (int h = 0; h < 2; ++h) {
      int d = lane * 4 + h * 128;
      float4 qv = __ldg((const float4*)(q + d));
      float4 rv = __ldg((const float4*)(rsm + d));
      float4 dq, qst, nr;
      dq.x = __fadd_rn(qv.x, -rv.x); dq.y = __fadd_rn(qv.y, -rv.y);
      dq.z = __fadd_rn(qv.z, -rv.z); dq.w = __fadd_rn(qv.w, -rv.w);
      qst.x = __fadd_rn(rv.x, dq.x); qst.y = __fadd_rn(rv.y, dq.y);
      qst.z = __fadd_rn(rv.z, dq.z); qst.w = __fadd_rn(rv.w, dq.w);
      nr.x = __fadd_rn(rv.x, -qst.x); nr.y = __fadd_rn(rv.y, -qst.y);
      nr.z = __fadd_rn(rv.z, -qst.z); nr.w = __fadd_rn(rv.w, -qst.w);
      *(float4*)(resp + d) = nr;
      float4 ov;
      if (layer == 0) {
        ov = qst;
      } else {
        ov = *(const float4*)(outp + d);
        ov.x = __fadd_rn(ov.x, qst.x); ov.y = __fadd_rn(ov.y, qst.y);
        ov.z = __fadd_rn(ov.z, qst.z); ov.w = __fadd_rn(ov.w, qst.w);
      }
      *(float4*)(outp + d) = ov;
      lsum += __fmul_rn(dq.x, dq.x) + __fmul_rn(dq.y, dq.y)
            + __fmul_rn(dq.z, dq.z) + __fmul_rn(dq.w, dq.w);
      if (layer < NUM_Q - 1) {
        __nv_bfloat16 hx = __float2bfloat16(nr.x);
        __nv_bfloat16 hy = __float2bfloat16(nr.y);
        __nv_bfloat16 hz = __float2bfloat16(nr.z);
        __nv_bfloat16 hw = __float2bfloat16(nr.w);
        __nv_bfloat16 lx = __float2bfloat16(__fsub_rn(nr.x, __bfloat162float(hx)));
        __nv_bfloat16 ly = __float2bfloat16(__fsub_rn(nr.y, __bfloat162float(hy)));
        __nv_bfloat16 lz = __float2bfloat16(__fsub_rn(nr.z, __bfloat162float(hz)));
        __nv_bfloat16 lw = __float2bfloat16(__fsub_rn(nr.w, __bfloat162float(hw)));
        __nv_bfloat162 h01, h23, l01, l23;
        h01.x = hx; h01.y = hy; h23.x = hz; h23.y = hw;
        l01.x = lx; l01.y = ly; l23.x = lz; l23.y = lw;
        uint2 hv, lv;
        hv.x = *(uint32_t*)&h01; hv.y = *(uint32_t*)&h23;
        lv.x = *(uint32_t*)&l01; lv.y = *(uint32_t*)&l23;
        *(uint2*)(arow + d)       = hv;
        *(uint2*)(arow + 256 + d) = hv;
        *(uint2*)(arow + 512 + d) = lv;
      }
    }
    if (lane == 0) atomicAdd(&g_counts[layer * N_EMBED + cc], 1);
  }
  #pragma unroll
  for (int off = 16; off > 0; off >>= 1)
    lsum += __shfl_xor_sync(0xffffffff, lsum, off);
  if (lane == 0) sRed[wid] = lsum;
  __syncthreads();
  if (tid == 0) {
    float s = 0.f;
    #pragma unroll
    for (int w = 0; w < NWARP; ++w) s += sRed[w];
    g_losspart[layer * NBLK + blockIdx.x] = s;
  }
}

// ---------------- finalize: loss mean + perplexity ----------------
__global__ void finalize_kernel(float* __restrict__ out) {
  const int l = blockIdx.x;
  const int tid = threadIdx.x;
  __shared__ double sd[256];
  __shared__ float  sf[256];
  double ls = 0.0;
  float  es = 0.f;
  for (int i = tid; i < NBLK; i += 256)
    ls += (double)g_losspart[l * NBLK + i];
  for (int i = tid; i < N_EMBED; i += 256) {
    float p = (float)g_counts[l * N_EMBED + i] * (1.0f / (float)NROWS);
    es += p * logf(__fadd_rn(p, 1e-10f));
  }
  sd[tid] = ls; sf[tid] = es;
  __syncthreads();
  for (int s = 128; s > 0; s >>= 1) {
    if (tid < s) { sd[tid] += sd[tid + s]; sf[tid] += sf[tid + s]; }
    __syncthreads();
  }
  if (tid == 0) {
    out[QOUT_ELEMS + l]         = (float)(sd[0] / (double)QOUT_ELEMS);
    out[QOUT_ELEMS + NUM_Q + l] = expf(-sf[0]);
  }
}

extern "C" void kernel_launch(void* const* d_in, const int* in_sizes, int n_in,
                              void* d_out, int out_size) {
  const float* x      = (const float*)d_in[0];
  const float* embeds = (const float*)d_in[1];
  float* out          = (float*)d_out;

  cudaFuncSetAttribute(vq_mma_kernel,
                       cudaFuncAttributeMaxDynamicSharedMemorySize, SMEM_TOTAL);

  prep_kernel<<<(NUM_Q * N_EMBED * DIM) / 256, 256>>>(embeds);
  norms_kernel<<<(NUM_Q * N_EMBED) / 256, 256>>>(embeds);
  convertA_kernel<<<(NROWS * DIM) / 256, 256>>>(x);

  for (int l = 0; l < NUM_Q; ++l) {
    vq_mma_kernel<<<NBLK, THREADS, SMEM_TOTAL>>>(x, out, l);
  }
  finalize_kernel<<<NUM_Q, 256>>>(out);
}

// round 14
// speedup vs baseline: 2.2707x; 2.0139x over previous
#include <cuda_runtime.h>
#include <cuda_fp16.h>
#include <math.h>
#include <stdint.h>

#define NUM_Q   8
#define DIM     256
#define N_EMBED 1024
#define NROWS   65536
#define QOUT_ELEMS (NROWS * DIM)

#define MCTA   128
#define KTOT   256                 // single fp16 plane
#define KCH    64
#define NKC    4                   // k-chunks per n-tile
#define NNT    8                   // n-tiles of 128 codes
#define NCH    (NNT * NKC)         // 32 chunks
#define NBLK   (NROWS / MCTA)      // 512
#define THREADS 256
#define NWARP  8
#define TAU    0.12f
#define NC     4

// smem layout (bytes) — 2 pipeline buffers for 2 CTAs/SM
#define BUF_SZ   32768             // A(16KB)+B(16KB) per chunk buffer
#define OFF_EN   (2 * BUF_SZ)      // 65536: 1024 floats
#define OFF_RN   (OFF_EN + 4096)   // 69632
#define OFF_IND  (OFF_RN + 512)    // 70144
#define OFF_RED  (OFF_IND + 512)   // 70656
#define OFF_CV   (OFF_RED + 128)   // 70784
#define OFF_CI   (OFF_CV + 16384)  // 87168
#define SMEM_TOTAL (OFF_CI + 16384)   // 103552

__device__ float g_res[NROWS * DIM];
__device__ float g_embT[NUM_Q * N_EMBED * DIM];
__device__ float g_norms[NUM_Q * N_EMBED];
__device__ float g_losspart[NUM_Q * NBLK];
__device__ int   g_counts[NUM_Q * N_EMBED];
__device__ __half g_Ah[(size_t)NROWS * KTOT];               // 32 MB
__device__ __half g_Bh[(size_t)NUM_Q * N_EMBED * KTOT];     // 4 MB

__device__ __forceinline__ uint32_t smem_u32(const void* p) {
  uint32_t a;
  asm("{ .reg .u64 t; cvta.to.shared.u64 t, %1; cvt.u32.u64 %0, t; }"
      : "=r"(a) : "l"(p));
  return a;
}
__device__ __forceinline__ void cp16(uint32_t dst, const void* src) {
  asm volatile("cp.async.cg.shared.global [%0], [%1], 16;"
               :: "r"(dst), "l"(src) : "memory");
}
__device__ __forceinline__ void cp_commit() {
  asm volatile("cp.async.commit_group;" ::: "memory");
}
#define LDSM_X4(r0, r1, r2, r3, addr) \
  asm volatile("ldmatrix.sync.aligned.m8n8.x4.shared.b16 {%0,%1,%2,%3}, [%4];" \
      : "=r"(r0), "=r"(r1), "=r"(r2), "=r"(r3) : "r"(addr))
__device__ __forceinline__ void mma_f16(float* d, const uint32_t* a,
                                        uint32_t b0, uint32_t b1) {
  asm volatile(
      "mma.sync.aligned.m16n8k16.row.col.f32.f16.f16.f32 "
      "{%0,%1,%2,%3}, {%4,%5,%6,%7}, {%8,%9}, {%0,%1,%2,%3};"
      : "+f"(d[0]), "+f"(d[1]), "+f"(d[2]), "+f"(d[3])
      : "r"(a[0]), "r"(a[1]), "r"(a[2]), "r"(a[3]), "r"(b0), "r"(b1));
}
__device__ __forceinline__ void ins4(float v, int c, float* cv, int* ci) {
  if (v < cv[NC - 1]) {
    float pv = v; int pc = c;
    #pragma unroll
    for (int q = 0; q < NC; ++q) {
      if (pv < cv[q]) {
        float tv = cv[q]; int tc = ci[q];
        cv[q] = pv; ci[q] = pc; pv = tv; pc = tc;
      }
    }
  }
}

// ---------------- prep: embT transpose + counts zero + B fp16 ----------------
__global__ void prep_kernel(const float* __restrict__ embeds) {
  int idx = blockIdx.x * 256 + threadIdx.x;   // over [l][d][k]
  int l = idx >> 18;
  int rem = idx & 262143;
  int d = rem >> 10;
  int k = rem & 1023;
  float v = embeds[idx];
  g_embT[((size_t)l * N_EMBED + k) * DIM + d] = v;
  g_Bh[((size_t)l * N_EMBED + k) * KTOT + d] = __float2half_rn(v);
  if (idx < NUM_Q * N_EMBED) g_counts[idx] = 0;
}

// ---------------- code norms: sequential d, separate mul+add ----------------
__global__ void norms_kernel(const float* __restrict__ embeds) {
  int k = blockIdx.x * 256 + threadIdx.x;
  int l = k >> 10;
  int kk = k & 1023;
  float s = 0.f;
  for (int d = 0; d < DIM; ++d) {
    float v = embeds[((size_t)l * DIM + d) * N_EMBED + kk];
    s = __fadd_rn(s, __fmul_rn(v, v));
  }
  g_norms[k] = s;
}

// ---------------- layer-0 A fp16 convert ----------------
__global__ void convertA_kernel(const float* __restrict__ x) {
  size_t idx = (size_t)blockIdx.x * 256 + threadIdx.x;
  g_Ah[idx] = __float2half_rn(x[idx]);
}

// ---------------- main fused VQ layer: ldmatrix + mma.sync fp16 + exact rescore ----------------
__global__ void __launch_bounds__(THREADS, 2)
vq_mma_kernel(const float* __restrict__ x,
              float* __restrict__ qout,
              int layer) {
  extern __shared__ char sm[];
  const uint32_t sbase = smem_u32(sm);
  float* sEN  = (float*)(sm + OFF_EN);
  float* sRN  = (float*)(sm + OFF_RN);
  int*   sInd = (int*)(sm + OFF_IND);
  float* sRed = (float*)(sm + OFF_RED);
  float* sCV  = (float*)(sm + OFF_CV);
  int*   sCI  = (int*)(sm + OFF_CI);

  const int tid = threadIdx.x, wid = tid >> 5, lane = tid & 31;
  const int mw = wid & 3;          // m-warp: rows mw*32..+31
  const int nw = wid >> 2;         // n-warp: codes nw*64..+63 within tile
  const int lr = lane >> 2;        // 0..7
  const int lc = lane & 3;         // 0..3

  const float* resin = (layer == 0) ? x : g_res;
  const float* rbase = resin + (size_t)blockIdx.x * MCTA * DIM;
  const __half* Ag = g_Ah + (size_t)blockIdx.x * MCTA * KTOT;
  const __half* Bg = g_Bh + (size_t)layer * N_EMBED * KTOT;

  // ldmatrix per-lane base offsets (bytes), swizzle baked in
  const int rowA0 = mw * 32 + (lane & 15);
  const int rowA1 = rowA0 + 16;
  const int halfA = lane >> 4;
  const uint32_t preA0 = (uint32_t)(rowA0 * 32 + ((halfA ^ ((rowA0 >> 2) & 1)) * 16));
  const uint32_t preA1 = (uint32_t)(rowA1 * 32 + ((halfA ^ ((rowA1 >> 2) & 1)) * 16));
  const int rowB  = nw * 64 + (lane & 7) + ((lane >> 4) & 1) * 8;
  const int halfB = (lane >> 3) & 1;
  const uint32_t preB = (uint32_t)(rowB * 32 + ((halfB ^ ((rowB >> 2) & 1)) * 16));

  // code norms into smem
  for (int i = tid; i < N_EMBED; i += THREADS)
    sEN[i] = g_norms[layer * N_EMBED + i];

  // ---- ||r||^2 per row (XLA row-reduce pattern; 16 rows per warp) ----
  #pragma unroll 1
  for (int rr = 0; rr < 16; ++rr) {
    int row = wid * 16 + rr;
    const float* rp = rbase + row * DIM;
    float p0 = 0.f, p1 = 0.f;
    #pragma unroll
    for (int i = 0; i < 4; ++i) {
      float2 v = __ldg((const float2*)&rp[i * 64 + 2 * lane]);
      p0 = __fadd_rn(p0, __fmul_rn(v.x, v.x));
      p1 = __fadd_rn(p1, __fmul_rn(v.y, v.y));
    }
    float a = __fadd_rn(p0, p1);
    #pragma unroll
    for (int off = 16; off > 0; off >>= 1)
      a = __fadd_rn(a, __shfl_down_sync(0xffffffff, a, off));
    if (lane == 0) sRN[row] = a;
  }

  // chunk fill via cp.async (layout: [ks][row][half], half-bit XOR swizzle)
  auto fill = [&](int ch) {
    const int nt = ch >> 2, kc = ch & 3;
    const uint32_t base = sbase + (uint32_t)(ch & 1) * BUF_SZ;
    #pragma unroll
    for (int t = 0; t < 4; ++t) {
      int idx = tid + t * THREADS;      // 0..1023
      int row = idx >> 3, seg = idx & 7;
      int ks = seg >> 1, half = seg & 1;
      uint32_t off = (uint32_t)(ks * 4096 + row * 32
                                + ((half ^ ((row >> 2) & 1)) * 16));
      cp16(base + off, Ag + (size_t)row * KTOT + kc * KCH + seg * 8);
      cp16(base + 16384 + off,
           Bg + (size_t)(nt * 128 + row) * KTOT + kc * KCH + seg * 8);
    }
    cp_commit();
  };

  fill(0); fill(1);

  float acc[2][8][4];
  float cv[4][NC]; int ci[4][NC];
  #pragma unroll
  for (int li = 0; li < 4; ++li)
    #pragma unroll
    for (int q = 0; q < NC; ++q) { cv[li][q] = 3.4028235e38f; ci[li][q] = 0; }

  for (int c = 0; c < NCH; ++c) {
    const int nt = c >> 2, kc = c & 3;

    if (c + 1 < NCH) asm volatile("cp.async.wait_group 1;" ::: "memory");
    else             asm volatile("cp.async.wait_group 0;" ::: "memory");
    __syncthreads();

    if (kc == 0) {
      #pragma unroll
      for (int i = 0; i < 2; ++i)
        #pragma unroll
        for (int j = 0; j < 8; ++j)
          #pragma unroll
          for (int q = 0; q < 4; ++q) acc[i][j][q] = 0.f;
    }

    const uint32_t base = sbase + (uint32_t)(c & 1) * BUF_SZ;
    #pragma unroll
    for (int ks = 0; ks < 4; ++ks) {
      uint32_t a0[4], a1[4];
      LDSM_X4(a0[0], a0[1], a0[2], a0[3], base + preA0 + ks * 4096);
      LDSM_X4(a1[0], a1[1], a1[2], a1[3], base + preA1 + ks * 4096);
      #pragma unroll
      for (int p = 0; p < 4; ++p) {
        uint32_t b0, b1, b2, b3;
        LDSM_X4(b0, b1, b2, b3, base + 16384 + preB + ks * 4096 + p * 512);
        mma_f16(acc[0][p * 2],     a0, b0, b1);
        mma_f16(acc[0][p * 2 + 1], a0, b2, b3);
        mma_f16(acc[1][p * 2],     a1, b0, b1);
        mma_f16(acc[1][p * 2 + 1], a1, b2, b3);
      }
    }

    if (kc == NKC - 1) {
      const int C00 = nt * 128 + nw * 64 + lc * 2;
      #pragma unroll
      for (int i = 0; i < 2; ++i) {
        #pragma unroll
        for (int j = 0; j < 8; ++j) {
          int code0 = C00 + j * 8;
          float e0 = sEN[code0], e1 = sEN[code0 + 1];
          ins4(__fmaf_rn(-2.f, acc[i][j][0], e0), code0,     cv[i * 2],     ci[i * 2]);
          ins4(__fmaf_rn(-2.f, acc[i][j][1], e1), code0 + 1, cv[i * 2],     ci[i * 2]);
          ins4(__fmaf_rn(-2.f, acc[i][j][2], e0), code0,     cv[i * 2 + 1], ci[i * 2 + 1]);
          ins4(__fmaf_rn(-2.f, acc[i][j][3], e1), code0 + 1, cv[i * 2 + 1], ci[i * 2 + 1]);
        }
      }
    }

    __syncthreads();                  // all warps done reading buffer (c&1)
    if (c + 2 < NCH) fill(c + 2);     // refill it for chunk c+2
  }

  // dump candidates: row r has 32 slots (2 nw x 4 lc x NC)
  {
    const int slot = nw * 16 + lc * 4;
    #pragma unroll
    for (int i = 0; i < 2; ++i)
      #pragma unroll
      for (int a = 0; a < 2; ++a) {
        int r = mw * 32 + i * 16 + a * 8 + lr;
        int li = i * 2 + a;
        #pragma unroll
        for (int q = 0; q < NC; ++q) {
          sCV[r * 32 + slot + q] = cv[li][q];
          sCI[r * 32 + slot + q] = ci[li][q];
        }
      }
  }
  __syncthreads();

  // ---- exact rescore (bit-identical reference chain) ----
  if (tid < MCTA) {
    const int r = tid;
    float vmin = 3.4028235e38f;
    #pragma unroll 4
    for (int s = 0; s < 32; ++s) vmin = fminf(vmin, sCV[r * 32 + s]);
    const float thr = vmin + TAU;
    const float rn = sRN[r];
    const float* rp = rbase + r * DIM;
    float bestd = 3.4028235e38f;
    int   bestc = 0x7fffffff;
    #pragma unroll 1
    for (int s = 0; s < 32; ++s) {
      if (sCV[r * 32 + s] <= thr) {
        int code = sCI[r * 32 + s];
        const float* ep = g_embT + ((size_t)layer * N_EMBED + code) * DIM;
        float ab = 0.f;
        #pragma unroll 8
        for (int d4 = 0; d4 < 64; ++d4) {
          float4 rv = __ldg((const float4*)rp + d4);
          float4 ev = __ldg((const float4*)ep + d4);
          ab = __fmaf_rn(rv.x, ev.x, ab);
          ab = __fmaf_rn(rv.y, ev.y, ab);
          ab = __fmaf_rn(rv.z, ev.z, ab);
          ab = __fmaf_rn(rv.w, ev.w, ab);
        }
        float en = sEN[code];
        float dist = __fadd_rn(__fadd_rn(rn, __fmul_rn(-2.0f, ab)), en);
        if (dist < bestd || (dist == bestd && code < bestc)) {
          bestd = dist; bestc = code;
        }
      }
    }
    sInd[r] = bestc;
  }
  __syncthreads();

  // ---- straight-through epilogue (exact chain) + fused next-layer A fp16 ----
  float lsum = 0.f;
  const size_t rowbase = (size_t)blockIdx.x * MCTA;
  #pragma unroll 1
  for (int rr = 0; rr < 16; ++rr) {
    int r = wid * 16 + rr;
    int cc = sInd[r];
    const float* q   = g_embT + ((size_t)layer * N_EMBED + cc) * DIM;
    float* outp      = qout  + (rowbase + r) * DIM;
    float* resp      = g_res + (rowbase + r) * DIM;
    const float* rsm = rbase + r * DIM;
    __half* arow = g_Ah + (rowbase + r) * KTOT;
    #pragma unroll
    for (int h = 0; h < 2; ++h) {
      int d = lane * 4 + h * 128;
      float4 qv = __ldg((const float4*)(q + d));
      float4 rv = __ldg((const float4*)(rsm + d));
      float4 dq, qst, nr;
      dq.x = __fadd_rn(qv.x, -rv.x); dq.y = __fadd_rn(qv.y, -rv.y);
      dq.z = __fadd_rn(qv.z, -rv.z); dq.w = __fadd_rn(qv.w, -rv.w);
      qst.x = __fadd_rn(rv.x, dq.x); qst.y = __fadd_rn(rv.y, dq.y);
      qst.z = __fadd_rn(rv.z, dq.z); qst.w = __fadd_rn(rv.w, dq.w);
      nr.x = __fadd_rn(rv.x, -qst.x); nr.y = __fadd_rn(rv.y, -qst.y);
      nr.z = __fadd_rn(rv.z, -qst.z); nr.w = __fadd_rn(rv.w, -qst.w);
      *(float4*)(resp + d) = nr;
      float4 ov;
      if (layer == 0) {
        ov = qst;
      } else {
        ov = *(const float4*)(outp + d);
        ov.x = __fadd_rn(ov.x, qst.x); ov.y = __fadd_rn(ov.y, qst.y);
        ov.z = __fadd_rn(ov.z, qst.z); ov.w = __fadd_rn(ov.w, qst.w);
      }
      *(float4*)(outp + d) = ov;
      lsum += __fmul_rn(dq.x, dq.x) + __fmul_rn(dq.y, dq.y)
            + __fmul_rn(dq.z, dq.z) + __fmul_rn(dq.w, dq.w);
      if (layer < NUM_Q - 1) {
        __half2 h01, h23;
        h01.x = __float2half_rn(nr.x); h01.y = __float2half_rn(nr.y);
        h23.x = __float2half_rn(nr.z); h23.y = __float2half_rn(nr.w);
        uint2 hv;
        hv.x = *(uint32_t*)&h01; hv.y = *(uint32_t*)&h23;
        *(uint2*)(arow + d) = hv;
      }
    }
    if (lane == 0) atomicAdd(&g_counts[layer * N_EMBED + cc], 1);
  }
  #pragma unroll
  for (int off = 16; off > 0; off >>= 1)
    lsum += __shfl_xor_sync(0xffffffff, lsum, off);
  if (lane == 0) sRed[wid] = lsum;
  __syncthreads();
  if (tid == 0) {
    float s = 0.f;
    #pragma unroll
    for (int w = 0; w < NWARP; ++w) s += sRed[w];
    g_losspart[layer * NBLK + blockIdx.x] = s;
  }
}

// ---------------- finalize: loss mean + perplexity ----------------
__global__ void finalize_kernel(float* __restrict__ out) {
  const int l = blockIdx.x;
  const int tid = threadIdx.x;
  __shared__ double sd[256];
  __shared__ float  sf[256];
  double ls = 0.0;
  float  es = 0.f;
  for (int i = tid; i < NBLK; i += 256)
    ls += (double)g_losspart[l * NBLK + i];
  for (int i = tid; i < N_EMBED; i += 256) {
    float p = (float)g_counts[l * N_EMBED + i] * (1.0f / (float)NROWS);
    es += p * logf(__fadd_rn(p, 1e-10f));
  }
  sd[tid] = ls; sf[tid] = es;
  __syncthreads();
  for (int s = 128; s > 0; s >>= 1) {
    if (tid < s) { sd[tid] += sd[tid + s]; sf[tid] += sf[tid + s]; }
    __syncthreads();
  }
  if (tid == 0) {
    out[QOUT_ELEMS + l]         = (float)(sd[0] / (double)QOUT_ELEMS);
    out[QOUT_ELEMS + NUM_Q + l] = expf(-sf[0]);
  }
}

extern "C" void kernel_launch(void* const* d_in, const int* in_sizes, int n_in,
                              void* d_out, int out_size) {
  const float* x      = (const float*)d_in[0];
  const float* embeds = (const float*)d_in[1];
  float* out          = (float*)d_out;

  cudaFuncSetAttribute(vq_mma_kernel,
                       cudaFuncAttributeMaxDynamicSharedMemorySize, SMEM_TOTAL);

  prep_kernel<<<(NUM_Q * N_EMBED * DIM) / 256, 256>>>(embeds);
  norms_kernel<<<(NUM_Q * N_EMBED) / 256, 256>>>(embeds);
  convertA_kernel<<<(NROWS * DIM) / 256, 256>>>(x);

  for (int l = 0; l < NUM_Q; ++l) {
    vq_mma_kernel<<<NBLK, THREADS, SMEM_TOTAL>>>(x, out, l);
  }
  finalize_kernel<<<NUM_Q, 256>>>(out);
}